// round 4
// baseline (speedup 1.0000x reference)
#include <cuda_runtime.h>
#include <math_constants.h>

#define B_  2
#define L_  2048
#define D_  1024
#define H_  16
#define DH_ 64

// Scratch for q, k, v projections ([B, L, D] each, fp32)
__device__ float g_q[B_ * L_ * D_];
__device__ float g_k[B_ * L_ * D_];
__device__ float g_v[B_ * L_ * D_];

// ---------------------------------------------------------------------------
// QKV projection: y = x @ W^T + b for W in {Wq, Wk, Wv} (blockIdx.z selects)
// Tiles: BM=BN=128, BK=16. 256 threads, 8x8 micro-tile per thread.
// SMEM stored k-major (transposed) so compute loads are contiguous LDS.128.
// ---------------------------------------------------------------------------
__global__ __launch_bounds__(256) void qkv_kernel(
    const float* __restrict__ x,
    const float* __restrict__ Wq, const float* __restrict__ bq,
    const float* __restrict__ Wk, const float* __restrict__ bk,
    const float* __restrict__ Wv, const float* __restrict__ bv)
{
    const float* W;
    const float* bias;
    float* out;
    if (blockIdx.z == 0)      { W = Wq; bias = bq; out = g_q; }
    else if (blockIdx.z == 1) { W = Wk; bias = bk; out = g_k; }
    else                      { W = Wv; bias = bv; out = g_v; }

    __shared__ float Xs[16][132];   // [k][m], padded to keep 16B alignment
    __shared__ float Ws[16][132];   // [k][n]

    const int m0  = blockIdx.y * 128;
    const int n0  = blockIdx.x * 128;
    const int tid = threadIdx.x;
    const int ty  = tid >> 4;       // 0..15
    const int tx  = tid & 15;       // 0..15

    float acc[8][8];
#pragma unroll
    for (int i = 0; i < 8; i++)
#pragma unroll
        for (int j = 0; j < 8; j++) acc[i][j] = 0.f;

    const int lrow = tid >> 1;          // 0..127
    const int lseg = (tid & 1) * 8;     // 0 or 8

    const float* xg = x + (size_t)(m0 + lrow) * D_ + lseg;
    const float* wg = W + (size_t)(n0 + lrow) * D_ + lseg;

    for (int k0 = 0; k0 < D_; k0 += 16) {
        float4 a0 = *(const float4*)(xg + k0);
        float4 a1 = *(const float4*)(xg + k0 + 4);
        float4 b0 = *(const float4*)(wg + k0);
        float4 b1 = *(const float4*)(wg + k0 + 4);
        __syncthreads();
        Xs[lseg + 0][lrow] = a0.x; Xs[lseg + 1][lrow] = a0.y;
        Xs[lseg + 2][lrow] = a0.z; Xs[lseg + 3][lrow] = a0.w;
        Xs[lseg + 4][lrow] = a1.x; Xs[lseg + 5][lrow] = a1.y;
        Xs[lseg + 6][lrow] = a1.z; Xs[lseg + 7][lrow] = a1.w;
        Ws[lseg + 0][lrow] = b0.x; Ws[lseg + 1][lrow] = b0.y;
        Ws[lseg + 2][lrow] = b0.z; Ws[lseg + 3][lrow] = b0.w;
        Ws[lseg + 4][lrow] = b1.x; Ws[lseg + 5][lrow] = b1.y;
        Ws[lseg + 6][lrow] = b1.z; Ws[lseg + 7][lrow] = b1.w;
        __syncthreads();
#pragma unroll
        for (int k = 0; k < 16; k++) {
            float af[8], bf[8];
            *(float4*)&af[0] = *(const float4*)&Xs[k][ty * 8];
            *(float4*)&af[4] = *(const float4*)&Xs[k][ty * 8 + 4];
            *(float4*)&bf[0] = *(const float4*)&Ws[k][tx * 8];
            *(float4*)&bf[4] = *(const float4*)&Ws[k][tx * 8 + 4];
#pragma unroll
            for (int i = 0; i < 8; i++)
#pragma unroll
                for (int j = 0; j < 8; j++)
                    acc[i][j] = fmaf(af[i], bf[j], acc[i][j]);
        }
    }

#pragma unroll
    for (int i = 0; i < 8; i++) {
        const int m = m0 + ty * 8 + i;
#pragma unroll
        for (int j = 0; j < 8; j += 4) {
            const int n = n0 + tx * 8 + j;
            float4 r;
            r.x = acc[i][j + 0] + bias[n + 0];
            r.y = acc[i][j + 1] + bias[n + 1];
            r.z = acc[i][j + 2] + bias[n + 2];
            r.w = acc[i][j + 3] + bias[n + 3];
            *(float4*)&out[(size_t)m * D_ + n] = r;
        }
    }
}

// ---------------------------------------------------------------------------
// Causal flash attention. 64x64 tiles, DH=64. 256 threads = 16x16, each thread
// owns a 4x4 score/output micro-tile. Online softmax; 16-lane shfl reductions.
// Each CTA processes query blocks {x, 31-x} -> exactly 33 KV tiles per CTA.
// ---------------------------------------------------------------------------
__global__ __launch_bounds__(256) void attn_kernel(float* __restrict__ out)
{
    extern __shared__ float sm[];
    float* Qs = sm;                 // [d][r]  64 x 68 (scaled by 1/8)
    float* Ks = sm + 64 * 68;       // [d][c]  64 x 68
    float* Vs = sm + 2 * 64 * 68;   // [c][dv] 64 x 68
    float* Ps = sm + 3 * 64 * 68;   // [c][r]  64 x 68

    const int bh = blockIdx.y;
    const int b  = bh >> 4;
    const int h  = bh & 15;
    const int tid = threadIdx.x;
    const int ty  = tid >> 4;       // 0..15
    const int tx  = tid & 15;       // 0..15

    const size_t base = (size_t)b * L_ * D_ + (size_t)h * DH_;

    const int lr = tid >> 2;            // 0..63 (row for tile loads)
    const int ld0 = (tid & 3) * 16;     // 0,16,32,48

    for (int pass = 0; pass < 2; pass++) {
        const int qb = (pass == 0) ? (int)blockIdx.x : (31 - (int)blockIdx.x);
        const int q0 = qb * 64;

        __syncthreads();  // previous pass finished with all SMEM
        // Load Q tile (scaled), transposed into [d][r]
        {
            const float* qg = g_q + base + (size_t)(q0 + lr) * D_ + ld0;
#pragma unroll
            for (int u = 0; u < 4; u++) {
                float4 v = *(const float4*)(qg + u * 4);
                Qs[(ld0 + u * 4 + 0) * 68 + lr] = v.x * 0.125f;
                Qs[(ld0 + u * 4 + 1) * 68 + lr] = v.y * 0.125f;
                Qs[(ld0 + u * 4 + 2) * 68 + lr] = v.z * 0.125f;
                Qs[(ld0 + u * 4 + 3) * 68 + lr] = v.w * 0.125f;
            }
        }

        float o[4][4];
        float mrow[4], lrow[4];
#pragma unroll
        for (int i = 0; i < 4; i++) {
            mrow[i] = -CUDART_INF_F;
            lrow[i] = 0.f;
#pragma unroll
            for (int j = 0; j < 4; j++) o[i][j] = 0.f;
        }

        for (int kb = 0; kb <= qb; kb++) {
            const int k0 = kb * 64;
            __syncthreads();  // prior tile consumers done (also covers Q store on kb=0)
            // Load K transposed [d][c], V direct [c][dv]
            {
                const float* kg = g_k + base + (size_t)(k0 + lr) * D_ + ld0;
                const float* vg = g_v + base + (size_t)(k0 + lr) * D_ + ld0;
#pragma unroll
                for (int u = 0; u < 4; u++) {
                    float4 kv = *(const float4*)(kg + u * 4);
                    Ks[(ld0 + u * 4 + 0) * 68 + lr] = kv.x;
                    Ks[(ld0 + u * 4 + 1) * 68 + lr] = kv.y;
                    Ks[(ld0 + u * 4 + 2) * 68 + lr] = kv.z;
                    Ks[(ld0 + u * 4 + 3) * 68 + lr] = kv.w;
                    float4 vv = *(const float4*)(vg + u * 4);
                    *(float4*)&Vs[lr * 68 + ld0 + u * 4] = vv;
                }
            }
            __syncthreads();

            // S = (Q/8) @ K^T  (4x4 per thread, reduce over d=64)
            float s[4][4];
#pragma unroll
            for (int i = 0; i < 4; i++)
#pragma unroll
                for (int j = 0; j < 4; j++) s[i][j] = 0.f;
#pragma unroll
            for (int d = 0; d < 64; d++) {
                float4 a = *(const float4*)&Qs[d * 68 + ty * 4];
                float4 bb = *(const float4*)&Ks[d * 68 + tx * 4];
                const float af[4] = {a.x, a.y, a.z, a.w};
                const float bf[4] = {bb.x, bb.y, bb.z, bb.w};
#pragma unroll
                for (int i = 0; i < 4; i++)
#pragma unroll
                    for (int j = 0; j < 4; j++)
                        s[i][j] = fmaf(af[i], bf[j], s[i][j]);
            }

            // Causal mask (only the diagonal tile needs it)
            if (kb == qb) {
#pragma unroll
                for (int i = 0; i < 4; i++) {
                    const int qr = q0 + ty * 4 + i;
#pragma unroll
                    for (int j = 0; j < 4; j++) {
                        const int kc = k0 + tx * 4 + j;
                        if (kc > qr) s[i][j] = -CUDART_INF_F;
                    }
                }
            }

            // Online softmax update
#pragma unroll
            for (int i = 0; i < 4; i++) {
                float mx = fmaxf(fmaxf(s[i][0], s[i][1]), fmaxf(s[i][2], s[i][3]));
                mx = fmaxf(mx, __shfl_xor_sync(0xffffffffu, mx, 1));
                mx = fmaxf(mx, __shfl_xor_sync(0xffffffffu, mx, 2));
                mx = fmaxf(mx, __shfl_xor_sync(0xffffffffu, mx, 4));
                mx = fmaxf(mx, __shfl_xor_sync(0xffffffffu, mx, 8));
                const float mn = fmaxf(mrow[i], mx);
                const float cf = __expf(mrow[i] - mn);   // 0 on first tile
                mrow[i] = mn;
                float rs = 0.f;
#pragma unroll
                for (int j = 0; j < 4; j++) {
                    s[i][j] = __expf(s[i][j] - mn);
                    rs += s[i][j];
                }
                rs += __shfl_xor_sync(0xffffffffu, rs, 1);
                rs += __shfl_xor_sync(0xffffffffu, rs, 2);
                rs += __shfl_xor_sync(0xffffffffu, rs, 4);
                rs += __shfl_xor_sync(0xffffffffu, rs, 8);
                lrow[i] = lrow[i] * cf + rs;
#pragma unroll
                for (int j = 0; j < 4; j++) o[i][j] *= cf;
            }

            // Store P transposed [c][r]
#pragma unroll
            for (int i = 0; i < 4; i++)
#pragma unroll
                for (int j = 0; j < 4; j++)
                    Ps[(tx * 4 + j) * 68 + (ty * 4 + i)] = s[i][j];
            __syncthreads();

            // O += P @ V (reduce over c=64)
#pragma unroll
            for (int c = 0; c < 64; c++) {
                float4 a = *(const float4*)&Ps[c * 68 + ty * 4];
                float4 bb = *(const float4*)&Vs[c * 68 + tx * 4];
                const float af[4] = {a.x, a.y, a.z, a.w};
                const float bf[4] = {bb.x, bb.y, bb.z, bb.w};
#pragma unroll
                for (int i = 0; i < 4; i++)
#pragma unroll
                    for (int j = 0; j < 4; j++)
                        o[i][j] = fmaf(af[i], bf[j], o[i][j]);
            }
        }

        // Epilogue: normalize and write [B, L, H*DH]
#pragma unroll
        for (int i = 0; i < 4; i++) {
            const float inv = 1.f / lrow[i];
            float4 r4;
            r4.x = o[i][0] * inv;
            r4.y = o[i][1] * inv;
            r4.z = o[i][2] * inv;
            r4.w = o[i][3] * inv;
            *(float4*)&out[base + (size_t)(q0 + ty * 4 + i) * D_ + tx * 4] = r4;
        }
    }
}

// ---------------------------------------------------------------------------
extern "C" void kernel_launch(void* const* d_in, const int* in_sizes, int n_in,
                              void* d_out, int out_size)
{
    const float* x  = (const float*)d_in[0];
    // d_in[1] = atten_mask (strict upper triangular; computed analytically, unused)
    const float* Wq = (const float*)d_in[2];
    const float* bq = (const float*)d_in[3];
    const float* Wk = (const float*)d_in[4];
    const float* bk = (const float*)d_in[5];
    const float* Wv = (const float*)d_in[6];
    const float* bv = (const float*)d_in[7];
    float* out = (float*)d_out;

    qkv_kernel<<<dim3(D_ / 128, (B_ * L_) / 128, 3), 256>>>(x, Wq, bq, Wk, bk, Wv, bv);

    const int smem = 4 * 64 * 68 * (int)sizeof(float);  // 69632 B
    cudaFuncSetAttribute(attn_kernel, cudaFuncAttributeMaxDynamicSharedMemorySize, smem);
    attn_kernel<<<dim3(L_ / 64 / 2, B_ * H_), 256, smem>>>(out);
}

// round 5
// speedup vs baseline: 1.0027x; 1.0027x over previous
#include <cuda_runtime.h>
#include <math_constants.h>

#define B_  2
#define L_  2048
#define D_  1024
#define H_  16
#define DH_ 64

// Scratch for q, k, v projections ([B, L, D] each, fp32)
__device__ float g_q[B_ * L_ * D_];
__device__ float g_k[B_ * L_ * D_];
__device__ float g_v[B_ * L_ * D_];

// ---------------------------------------------------------------------------
// QKV projection: y = x @ W^T + b for W in {Wq, Wk, Wv} (blockIdx.z selects)
// Tiles: BM=BN=128, BK=16. 256 threads, 8x8 micro-tile per thread.
// SMEM stored k-major (transposed) so compute loads are contiguous LDS.128.
// ---------------------------------------------------------------------------
__global__ __launch_bounds__(256) void qkv_kernel(
    const float* __restrict__ x,
    const float* __restrict__ Wq, const float* __restrict__ bq,
    const float* __restrict__ Wk, const float* __restrict__ bk,
    const float* __restrict__ Wv, const float* __restrict__ bv)
{
    const float* W;
    const float* bias;
    float* out;
    if (blockIdx.z == 0)      { W = Wq; bias = bq; out = g_q; }
    else if (blockIdx.z == 1) { W = Wk; bias = bk; out = g_k; }
    else                      { W = Wv; bias = bv; out = g_v; }

    __shared__ float Xs[16][132];   // [k][m], padded to keep 16B alignment
    __shared__ float Ws[16][132];   // [k][n]

    const int m0  = blockIdx.y * 128;
    const int n0  = blockIdx.x * 128;
    const int tid = threadIdx.x;
    const int ty  = tid >> 4;       // 0..15
    const int tx  = tid & 15;       // 0..15

    float acc[8][8];
#pragma unroll
    for (int i = 0; i < 8; i++)
#pragma unroll
        for (int j = 0; j < 8; j++) acc[i][j] = 0.f;

    const int lrow = tid >> 1;          // 0..127
    const int lseg = (tid & 1) * 8;     // 0 or 8

    const float* xg = x + (size_t)(m0 + lrow) * D_ + lseg;
    const float* wg = W + (size_t)(n0 + lrow) * D_ + lseg;

    for (int k0 = 0; k0 < D_; k0 += 16) {
        float4 a0 = *(const float4*)(xg + k0);
        float4 a1 = *(const float4*)(xg + k0 + 4);
        float4 b0 = *(const float4*)(wg + k0);
        float4 b1 = *(const float4*)(wg + k0 + 4);
        __syncthreads();
        Xs[lseg + 0][lrow] = a0.x; Xs[lseg + 1][lrow] = a0.y;
        Xs[lseg + 2][lrow] = a0.z; Xs[lseg + 3][lrow] = a0.w;
        Xs[lseg + 4][lrow] = a1.x; Xs[lseg + 5][lrow] = a1.y;
        Xs[lseg + 6][lrow] = a1.z; Xs[lseg + 7][lrow] = a1.w;
        Ws[lseg + 0][lrow] = b0.x; Ws[lseg + 1][lrow] = b0.y;
        Ws[lseg + 2][lrow] = b0.z; Ws[lseg + 3][lrow] = b0.w;
        Ws[lseg + 4][lrow] = b1.x; Ws[lseg + 5][lrow] = b1.y;
        Ws[lseg + 6][lrow] = b1.z; Ws[lseg + 7][lrow] = b1.w;
        __syncthreads();
#pragma unroll
        for (int k = 0; k < 16; k++) {
            float af[8], bf[8];
            *(float4*)&af[0] = *(const float4*)&Xs[k][ty * 8];
            *(float4*)&af[4] = *(const float4*)&Xs[k][ty * 8 + 4];
            *(float4*)&bf[0] = *(const float4*)&Ws[k][tx * 8];
            *(float4*)&bf[4] = *(const float4*)&Ws[k][tx * 8 + 4];
#pragma unroll
            for (int i = 0; i < 8; i++)
#pragma unroll
                for (int j = 0; j < 8; j++)
                    acc[i][j] = fmaf(af[i], bf[j], acc[i][j]);
        }
    }

#pragma unroll
    for (int i = 0; i < 8; i++) {
        const int m = m0 + ty * 8 + i;
#pragma unroll
        for (int j = 0; j < 8; j += 4) {
            const int n = n0 + tx * 8 + j;
            float4 r;
            r.x = acc[i][j + 0] + bias[n + 0];
            r.y = acc[i][j + 1] + bias[n + 1];
            r.z = acc[i][j + 2] + bias[n + 2];
            r.w = acc[i][j + 3] + bias[n + 3];
            *(float4*)&out[(size_t)m * D_ + n] = r;
        }
    }
}

// ---------------------------------------------------------------------------
// Causal flash attention. 64x64 tiles, DH=64. 256 threads = 16x16, each thread
// owns a 4x4 score/output micro-tile. Online softmax; 16-lane shfl reductions.
// Each CTA processes query blocks {x, 31-x} -> exactly 33 KV tiles per CTA.
// ---------------------------------------------------------------------------
__global__ __launch_bounds__(256) void attn_kernel(float* __restrict__ out)
{
    extern __shared__ float sm[];
    float* Qs = sm;                 // [d][r]  64 x 68 (scaled by 1/8)
    float* Ks = sm + 64 * 68;       // [d][c]  64 x 68
    float* Vs = sm + 2 * 64 * 68;   // [c][dv] 64 x 68
    float* Ps = sm + 3 * 64 * 68;   // [c][r]  64 x 68

    const int bh = blockIdx.y;
    const int b  = bh >> 4;
    const int h  = bh & 15;
    const int tid = threadIdx.x;
    const int ty  = tid >> 4;       // 0..15
    const int tx  = tid & 15;       // 0..15

    const size_t base = (size_t)b * L_ * D_ + (size_t)h * DH_;

    const int lr = tid >> 2;            // 0..63 (row for tile loads)
    const int ld0 = (tid & 3) * 16;     // 0,16,32,48

    for (int pass = 0; pass < 2; pass++) {
        const int qb = (pass == 0) ? (int)blockIdx.x : (31 - (int)blockIdx.x);
        const int q0 = qb * 64;

        __syncthreads();  // previous pass finished with all SMEM
        // Load Q tile (scaled), transposed into [d][r]
        {
            const float* qg = g_q + base + (size_t)(q0 + lr) * D_ + ld0;
#pragma unroll
            for (int u = 0; u < 4; u++) {
                float4 v = *(const float4*)(qg + u * 4);
                Qs[(ld0 + u * 4 + 0) * 68 + lr] = v.x * 0.125f;
                Qs[(ld0 + u * 4 + 1) * 68 + lr] = v.y * 0.125f;
                Qs[(ld0 + u * 4 + 2) * 68 + lr] = v.z * 0.125f;
                Qs[(ld0 + u * 4 + 3) * 68 + lr] = v.w * 0.125f;
            }
        }

        float o[4][4];
        float mrow[4], lrow[4];
#pragma unroll
        for (int i = 0; i < 4; i++) {
            mrow[i] = -CUDART_INF_F;
            lrow[i] = 0.f;
#pragma unroll
            for (int j = 0; j < 4; j++) o[i][j] = 0.f;
        }

        for (int kb = 0; kb <= qb; kb++) {
            const int k0 = kb * 64;
            __syncthreads();  // prior tile consumers done (also covers Q store on kb=0)
            // Load K transposed [d][c], V direct [c][dv]
            {
                const float* kg = g_k + base + (size_t)(k0 + lr) * D_ + ld0;
                const float* vg = g_v + base + (size_t)(k0 + lr) * D_ + ld0;
#pragma unroll
                for (int u = 0; u < 4; u++) {
                    float4 kv = *(const float4*)(kg + u * 4);
                    Ks[(ld0 + u * 4 + 0) * 68 + lr] = kv.x;
                    Ks[(ld0 + u * 4 + 1) * 68 + lr] = kv.y;
                    Ks[(ld0 + u * 4 + 2) * 68 + lr] = kv.z;
                    Ks[(ld0 + u * 4 + 3) * 68 + lr] = kv.w;
                    float4 vv = *(const float4*)(vg + u * 4);
                    *(float4*)&Vs[lr * 68 + ld0 + u * 4] = vv;
                }
            }
            __syncthreads();

            // S = (Q/8) @ K^T  (4x4 per thread, reduce over d=64)
            float s[4][4];
#pragma unroll
            for (int i = 0; i < 4; i++)
#pragma unroll
                for (int j = 0; j < 4; j++) s[i][j] = 0.f;
#pragma unroll
            for (int d = 0; d < 64; d++) {
                float4 a = *(const float4*)&Qs[d * 68 + ty * 4];
                float4 bb = *(const float4*)&Ks[d * 68 + tx * 4];
                const float af[4] = {a.x, a.y, a.z, a.w};
                const float bf[4] = {bb.x, bb.y, bb.z, bb.w};
#pragma unroll
                for (int i = 0; i < 4; i++)
#pragma unroll
                    for (int j = 0; j < 4; j++)
                        s[i][j] = fmaf(af[i], bf[j], s[i][j]);
            }

            // Causal mask (only the diagonal tile needs it)
            if (kb == qb) {
#pragma unroll
                for (int i = 0; i < 4; i++) {
                    const int qr = q0 + ty * 4 + i;
#pragma unroll
                    for (int j = 0; j < 4; j++) {
                        const int kc = k0 + tx * 4 + j;
                        if (kc > qr) s[i][j] = -CUDART_INF_F;
                    }
                }
            }

            // Online softmax update
#pragma unroll
            for (int i = 0; i < 4; i++) {
                float mx = fmaxf(fmaxf(s[i][0], s[i][1]), fmaxf(s[i][2], s[i][3]));
                mx = fmaxf(mx, __shfl_xor_sync(0xffffffffu, mx, 1));
                mx = fmaxf(mx, __shfl_xor_sync(0xffffffffu, mx, 2));
                mx = fmaxf(mx, __shfl_xor_sync(0xffffffffu, mx, 4));
                mx = fmaxf(mx, __shfl_xor_sync(0xffffffffu, mx, 8));
                const float mn = fmaxf(mrow[i], mx);
                const float cf = __expf(mrow[i] - mn);   // 0 on first tile
                mrow[i] = mn;
                float rs = 0.f;
#pragma unroll
                for (int j = 0; j < 4; j++) {
                    s[i][j] = __expf(s[i][j] - mn);
                    rs += s[i][j];
                }
                rs += __shfl_xor_sync(0xffffffffu, rs, 1);
                rs += __shfl_xor_sync(0xffffffffu, rs, 2);
                rs += __shfl_xor_sync(0xffffffffu, rs, 4);
                rs += __shfl_xor_sync(0xffffffffu, rs, 8);
                lrow[i] = lrow[i] * cf + rs;
#pragma unroll
                for (int j = 0; j < 4; j++) o[i][j] *= cf;
            }

            // Store P transposed [c][r]
#pragma unroll
            for (int i = 0; i < 4; i++)
#pragma unroll
                for (int j = 0; j < 4; j++)
                    Ps[(tx * 4 + j) * 68 + (ty * 4 + i)] = s[i][j];
            __syncthreads();

            // O += P @ V (reduce over c=64)
#pragma unroll
            for (int c = 0; c < 64; c++) {
                float4 a = *(const float4*)&Ps[c * 68 + ty * 4];
                float4 bb = *(const float4*)&Vs[c * 68 + tx * 4];
                const float af[4] = {a.x, a.y, a.z, a.w};
                const float bf[4] = {bb.x, bb.y, bb.z, bb.w};
#pragma unroll
                for (int i = 0; i < 4; i++)
#pragma unroll
                    for (int j = 0; j < 4; j++)
                        o[i][j] = fmaf(af[i], bf[j], o[i][j]);
            }
        }

        // Epilogue: normalize and write [B, L, H*DH]
#pragma unroll
        for (int i = 0; i < 4; i++) {
            const float inv = 1.f / lrow[i];
            float4 r4;
            r4.x = o[i][0] * inv;
            r4.y = o[i][1] * inv;
            r4.z = o[i][2] * inv;
            r4.w = o[i][3] * inv;
            *(float4*)&out[base + (size_t)(q0 + ty * 4 + i) * D_ + tx * 4] = r4;
        }
    }
}

// ---------------------------------------------------------------------------
extern "C" void kernel_launch(void* const* d_in, const int* in_sizes, int n_in,
                              void* d_out, int out_size)
{
    const float* x  = (const float*)d_in[0];
    // d_in[1] = atten_mask (strict upper triangular; computed analytically, unused)
    const float* Wq = (const float*)d_in[2];
    const float* bq = (const float*)d_in[3];
    const float* Wk = (const float*)d_in[4];
    const float* bk = (const float*)d_in[5];
    const float* Wv = (const float*)d_in[6];
    const float* bv = (const float*)d_in[7];
    float* out = (float*)d_out;

    qkv_kernel<<<dim3(D_ / 128, (B_ * L_) / 128, 3), 256>>>(x, Wq, bq, Wk, bk, Wv, bv);

    const int smem = 4 * 64 * 68 * (int)sizeof(float);  // 69632 B
    cudaFuncSetAttribute(attn_kernel, cudaFuncAttributeMaxDynamicSharedMemorySize, smem);
    attn_kernel<<<dim3(L_ / 64 / 2, B_ * H_), 256, smem>>>(out);
}